// round 5
// baseline (speedup 1.0000x reference)
#include <cuda_runtime.h>
#include <cuda_fp16.h>

// Problem: B=2, C=4, D=64, H=256, W=256
#define HW    65536        // H*W
#define DHW   4194304      // D*H*W
#define DHW4  1048576      // DHW/4
#define NQ    2097152      // B*DHW/4  (pass-1 threads, 4 voxels each)
#define NELEM 25165824.0   // B*(C-1)*DHW
#define CHUNK 16           // D planes marched per thread
#define NBLK2 512          // pass-2 blocks: 2*4*256*64/256

// Scratch: per-voxel packed probs {h2(p1,p2), h2(p3,0)}. (B,D,H,W). 67 MB.
__device__ __align__(16) uint2 g_probs[2 * DHW];
__device__ double   g_acc;
__device__ unsigned g_done = 0;

__device__ __forceinline__ unsigned h2u(__half2 h) { return *(unsigned*)&h; }
__device__ __forceinline__ __half2 u2h(unsigned u) { return *(__half2*)&u; }

// ---------------- Pass 1: softmax (4 voxels/thread), packed fp16 store --------
__global__ void __launch_bounds__(256)
softmax_kernel(const float* __restrict__ logits) {
    int t = blockIdx.x * blockDim.x + threadIdx.x;
    if (t == 0) g_acc = 0.0;
    if (t >= NQ) return;
    int b  = t >> 20;
    int v4 = t & (DHW4 - 1);
    const float4* L = (const float4*)logits + (size_t)b * 4 * DHW4 + v4;
    float4 x0 = L[0 * DHW4];
    float4 x1 = L[1 * DHW4];
    float4 x2 = L[2 * DHW4];
    float4 x3 = L[3 * DHW4];
    float4 p1, p2, p3;
#define SM1(comp) {                                                       \
        float a = x0.comp, bb = x1.comp, c = x2.comp, dd = x3.comp;       \
        float m  = fmaxf(fmaxf(a, bb), fmaxf(c, dd));                     \
        float e0 = __expf(a - m), e1 = __expf(bb - m);                    \
        float e2 = __expf(c - m), e3 = __expf(dd - m);                    \
        float inv = __frcp_rn(e0 + e1 + e2 + e3);                        \
        p1.comp = e1 * inv; p2.comp = e2 * inv; p3.comp = e3 * inv; }
    SM1(x) SM1(y) SM1(z) SM1(w)
#undef SM1
    uint4 s0, s1;
    s0.x = h2u(__floats2half2_rn(p1.x, p2.x)); s0.y = h2u(__floats2half2_rn(p3.x, 0.f));
    s0.z = h2u(__floats2half2_rn(p1.y, p2.y)); s0.w = h2u(__floats2half2_rn(p3.y, 0.f));
    s1.x = h2u(__floats2half2_rn(p1.z, p2.z)); s1.y = h2u(__floats2half2_rn(p3.z, 0.f));
    s1.z = h2u(__floats2half2_rn(p1.w, p2.w)); s1.w = h2u(__floats2half2_rn(p3.w, 0.f));
    uint4* dst = (uint4*)g_probs + ((size_t)b * (DHW / 2)) + ((size_t)v4 << 1);
    dst[0] = s0;
    dst[1] = s1;
}

// ---------------- Pass 2: D-marching stencil + loss + reduction ---------------
#define ENC(x) (1u << ((unsigned)(x) << 3))

__global__ void __launch_bounds__(256, 3)
loss_kernel(const int* __restrict__ targets, float* __restrict__ out) {
    int t  = blockIdx.x * blockDim.x + threadIdx.x;
    int w4 = t & 63;
    int h  = (t >> 6) & 255;
    int ck = (t >> 14) & 3;
    int b  = t >> 16;
    int dlo = ck * CHUNK;

    const uint2* Pb = g_probs + (size_t)b * DHW + h * 256 + (w4 << 2);
    const int*   Tb = targets + (size_t)b * DHW + h * 256 + (w4 << 2);

    const uint4 z4 = make_uint4(0, 0, 0, 0);
    const uint2 z2 = make_uint2(0, 0);
    const uint4 e0 = make_uint4(1, 1, 1, 1);   // ENC(class 0): pollutes byte 0 only
    const bool hok0 = (h > 0), hok1 = (h < 255);
    const bool wok0 = (w4 > 0), wok1 = (w4 < 63);
    const __half2 m6 = __floats2half2_rn(-6.f, -6.f);

#define LOADP(d0, d1, dd, cond) {                                              \
        if (cond) { const uint4* q_ = (const uint4*)(Pb + (size_t)(dd) * HW);  \
            d0 = q_[0]; d1 = q_[1]; }                                          \
        else { d0 = z4; d1 = z4; } }
#define LOADT(dst, dd, cond) {                                                 \
        if (cond) { int4 ti_ = *(const int4*)(Tb + (size_t)(dd) * HW);         \
            dst.x = ENC(ti_.x); dst.y = ENC(ti_.y);                            \
            dst.z = ENC(ti_.z); dst.w = ENC(ti_.w); }                          \
        else dst = e0; }

    uint4 pm0, pm1, pc0, pc1, pp0, pp1;
    uint4 em, ec, ep;
    LOADP(pm0, pm1, dlo - 1, dlo > 0)
    LOADT(em,       dlo - 1, dlo > 0)
    LOADP(pc0, pc1, dlo, true)
    LOADT(ec,       dlo, true)

    float acc = 0.f;

    for (int d = dlo; d < dlo + CHUNK; ++d) {
        // new far plane
        LOADP(pp0, pp1, d + 1, d < 63)
        LOADT(ep,       d + 1, d < 63)
        // fresh h/w taps for plane d
        const uint2* rowp = Pb + (size_t)d * HW;
        const int*   rowt = Tb + (size_t)d * HW;
        uint4 hm0, hm1, hp0, hp1, ehm, ehp;
        LOADP(hm0, hm1, 0, false)   // placeholder init (overwritten below)
        if (hok0) { const uint4* q_ = (const uint4*)(rowp - 256); hm0 = q_[0]; hm1 = q_[1]; }
        else      { hm0 = z4; hm1 = z4; }
        if (hok1) { const uint4* q_ = (const uint4*)(rowp + 256); hp0 = q_[0]; hp1 = q_[1]; }
        else      { hp0 = z4; hp1 = z4; }
        if (hok0) { int4 ti_ = *(const int4*)(rowt - 256);
            ehm.x = ENC(ti_.x); ehm.y = ENC(ti_.y); ehm.z = ENC(ti_.z); ehm.w = ENC(ti_.w); }
        else ehm = e0;
        if (hok1) { int4 ti_ = *(const int4*)(rowt + 256);
            ehp.x = ENC(ti_.x); ehp.y = ENC(ti_.y); ehp.z = ENC(ti_.z); ehp.w = ENC(ti_.w); }
        else ehp = e0;
        uint2 lfu = wok0 ? rowp[-1] : z2;
        uint2 rtu = wok1 ? rowp[4]  : z2;
        unsigned eL = wok0 ? ENC(rowt[-1]) : 1u;
        unsigned eR = wok1 ? ENC(rowt[4])  : 1u;

        // ---- half2 stencil: A = classes(1,2), B = class 3 ----
        __half2 cA[4], cB[4];
        cA[0] = u2h(pc0.x); cB[0] = u2h(pc0.y);
        cA[1] = u2h(pc0.z); cB[1] = u2h(pc0.w);
        cA[2] = u2h(pc1.x); cB[2] = u2h(pc1.y);
        cA[3] = u2h(pc1.z); cB[3] = u2h(pc1.w);

        __half2 sA[4], sB[4];
        sA[0] = __hadd2(u2h(lfu.x), cA[1]); sB[0] = __hadd2(u2h(lfu.y), cB[1]);
        sA[1] = __hadd2(cA[0], cA[2]);      sB[1] = __hadd2(cB[0], cB[2]);
        sA[2] = __hadd2(cA[1], cA[3]);      sB[2] = __hadd2(cB[1], cB[3]);
        sA[3] = __hadd2(cA[2], u2h(rtu.x)); sB[3] = __hadd2(cB[2], u2h(rtu.y));

#define ACCROW(r0, r1)                                                         \
        sA[0] = __hadd2(sA[0], u2h(r0.x)); sB[0] = __hadd2(sB[0], u2h(r0.y)); \
        sA[1] = __hadd2(sA[1], u2h(r0.z)); sB[1] = __hadd2(sB[1], u2h(r0.w)); \
        sA[2] = __hadd2(sA[2], u2h(r1.x)); sB[2] = __hadd2(sB[2], u2h(r1.y)); \
        sA[3] = __hadd2(sA[3], u2h(r1.z)); sB[3] = __hadd2(sB[3], u2h(r1.w));
        ACCROW(pm0, pm1)
        ACCROW(pp0, pp1)
        ACCROW(hm0, hm1)
        ACCROW(hp0, hp1)
#undef ACCROW
#pragma unroll
        for (int j = 0; j < 4; ++j) {
            sA[j] = __hfma2(cA[j], m6, sA[j]);
            sB[j] = __hfma2(cB[j], m6, sB[j]);
        }

        // ---- byte-packed target neighbor counts ----
        unsigned ns0 = em.x + ep.x + ehm.x + ehp.x + eL   + ec.y;
        unsigned ns1 = em.y + ep.y + ehm.y + ehp.y + ec.x + ec.z;
        unsigned ns2 = em.z + ep.z + ehm.z + ehp.z + ec.y + ec.w;
        unsigned ns3 = em.w + ep.w + ehm.w + ehp.w + ec.z + eR;
        unsigned nsv[4] = {ns0, ns1, ns2, ns3};
        unsigned ecv[4] = {ec.x, ec.y, ec.z, ec.w};

#pragma unroll
        for (int j = 0; j < 4; ++j) {
            float2 f12 = __half22float2(sA[j]);
            float  f3  = __half2float(__low2half(sB[j]));
            float lp[3] = {f12.x, f12.y, f3};
            unsigned n = nsv[j], e = ecv[j];
#pragma unroll
            for (int c1 = 1; c1 <= 3; ++c1) {
                int cnt = (int)((n >> (c1 * 8)) & 0xFFu);
                int isc = (int)((e >> (c1 * 8)) & 1u);
                float lt = (float)(cnt - 6 * isc);
                float diff = fabsf(lp[c1 - 1]) - fabsf(lt);
                acc = fmaf(diff, diff, acc);
            }
        }

        // rotate planes
        pm0 = pc0; pm1 = pc1; pc0 = pp0; pc1 = pp1;
        em = ec; ec = ep;
    }
#undef LOADP
#undef LOADT

    // ---- block reduction -> double atomic -> last-block finalize ----
#pragma unroll
    for (int o = 16; o; o >>= 1) acc += __shfl_down_sync(0xffffffffu, acc, o);
    __shared__ float ws[8];
    __shared__ unsigned ticket;
    int lane = threadIdx.x & 31, wid = threadIdx.x >> 5;
    if (lane == 0) ws[wid] = acc;
    __syncthreads();
    if (wid == 0) {
        acc = (lane < 8) ? ws[lane] : 0.f;
#pragma unroll
        for (int o = 4; o; o >>= 1) acc += __shfl_down_sync(0xffffffffu, acc, o);
        if (lane == 0) {
            atomicAdd(&g_acc, (double)acc);
            __threadfence();
            ticket = atomicAdd(&g_done, 1u);
        }
    }
    __syncthreads();
    if (threadIdx.x == 0 && ticket == gridDim.x - 1) {
        double total = atomicAdd(&g_acc, 0.0);
        out[0] = (float)(total * (1.0 / NELEM));
        g_done = 0;
    }
}

extern "C" void kernel_launch(void* const* d_in, const int* in_sizes, int n_in,
                              void* d_out, int out_size) {
    const float* logits  = (const float*)d_in[0];
    const int*   targets = (const int*)d_in[1];
    float* out = (float*)d_out;

    softmax_kernel<<<NQ / 256, 256>>>(logits);
    loss_kernel<<<NBLK2, 256>>>(targets, out);
}

// round 7
// speedup vs baseline: 1.2297x; 1.2297x over previous
#include <cuda_runtime.h>
#include <cuda_fp16.h>

// Problem: B=2, C=4, D=64, H=256, W=256
#define HW    65536        // H*W
#define DHW   4194304      // D*H*W
#define DHW4  1048576      // DHW/4
#define NQ    2097152      // B*DHW/4  (threads, 4 voxels each)
#define NELEM 25165824.0   // B*(C-1)*DHW

// Planar scratch: A = half2(p1,p2)/voxel (33.5MB), B = half(p3)/voxel (16.8MB),
// T = uint8 target/voxel (8.4MB)
__device__ __align__(16) __half2       g_A[2 * DHW];
__device__ __align__(16) __half        g_B[2 * DHW];
__device__ __align__(16) unsigned char g_T[2 * DHW];
__device__ double   g_acc;
__device__ unsigned g_done = 0;

__device__ __forceinline__ unsigned h2u(__half2 h) { return *(unsigned*)&h; }
__device__ __forceinline__ __half2 u2h(unsigned u) { return *(__half2*)&u; }

// ---------------- Pass 1: softmax + target byte-encode ----------------------
__global__ void __launch_bounds__(256)
softmax_kernel(const float* __restrict__ logits, const int* __restrict__ targets) {
    int t = blockIdx.x * blockDim.x + threadIdx.x;
    if (t == 0) g_acc = 0.0;
    if (t >= NQ) return;
    int b  = t >> 20;
    int v4 = t & (DHW4 - 1);
    const float4* L = (const float4*)logits + (size_t)b * 4 * DHW4 + v4;
    float4 x0 = L[0 * DHW4];
    float4 x1 = L[1 * DHW4];
    float4 x2 = L[2 * DHW4];
    float4 x3 = L[3 * DHW4];
    float4 p1, p2, p3;
#define SM1(comp) {                                                       \
        float a = x0.comp, bb = x1.comp, c = x2.comp, dd = x3.comp;       \
        float m  = fmaxf(fmaxf(a, bb), fmaxf(c, dd));                     \
        float e0 = __expf(a - m), e1 = __expf(bb - m);                    \
        float e2 = __expf(c - m), e3 = __expf(dd - m);                    \
        float inv = __frcp_rn(e0 + e1 + e2 + e3);                        \
        p1.comp = e1 * inv; p2.comp = e2 * inv; p3.comp = e3 * inv; }
    SM1(x) SM1(y) SM1(z) SM1(w)
#undef SM1
    size_t v = ((size_t)b * DHW) + ((size_t)v4 << 2);
    uint4 a4;
    a4.x = h2u(__floats2half2_rn(p1.x, p2.x));
    a4.y = h2u(__floats2half2_rn(p1.y, p2.y));
    a4.z = h2u(__floats2half2_rn(p1.z, p2.z));
    a4.w = h2u(__floats2half2_rn(p1.w, p2.w));
    *(uint4*)(g_A + v) = a4;
    uint2 b2;
    b2.x = h2u(__floats2half2_rn(p3.x, p3.y));
    b2.y = h2u(__floats2half2_rn(p3.z, p3.w));
    *(uint2*)(g_B + v) = b2;
    int4 tt = *((const int4*)targets + ((size_t)b * DHW4) + v4);
    unsigned tw = (unsigned)tt.x | ((unsigned)tt.y << 8)
                | ((unsigned)tt.z << 16) | ((unsigned)tt.w << 24);
    *(unsigned*)(g_T + v) = tw;
}

// ---------------- Pass 2: stencil + loss + reduction -------------------------
__global__ void __launch_bounds__(256, 5)
loss_kernel(float* __restrict__ out) {
    int t  = blockIdx.x * blockDim.x + threadIdx.x;
    int w4 = t & 63;
    int h  = (t >> 6) & 255;
    int d  = (t >> 14) & 63;
    int b  = t >> 20;
    size_t v = (size_t)d * HW + h * 256 + (w4 << 2);

    const __half2*       A  = g_A + (size_t)b * DHW;
    const __half*        Bp = g_B + (size_t)b * DHW;
    const unsigned char* Tb = g_T + (size_t)b * DHW;

    const bool d0ok = (d > 0), d1ok = (d < 63);
    const bool h0ok = (h > 0), h1ok = (h < 255);
    const bool w0ok = (w4 > 0), w1ok = (w4 < 63);
    const uint4 z4 = make_uint4(0, 0, 0, 0);
    const uint2 z2 = make_uint2(0, 0);

    // ---- loads (front-batched) ----
    uint4 Ac  = *(const uint4*)(A + v);
    uint4 Adm = d0ok ? *(const uint4*)(A + v - HW)  : z4;
    uint4 Adp = d1ok ? *(const uint4*)(A + v + HW)  : z4;
    uint4 Ahm = h0ok ? *(const uint4*)(A + v - 256) : z4;
    uint4 Ahp = h1ok ? *(const uint4*)(A + v + 256) : z4;
    unsigned lfA = w0ok ? *(const unsigned*)(A + v - 1) : 0u;
    unsigned rtA = w1ok ? *(const unsigned*)(A + v + 4) : 0u;

    uint2 Bc  = *(const uint2*)(Bp + v);
    uint2 Bdm = d0ok ? *(const uint2*)(Bp + v - HW)  : z2;
    uint2 Bdp = d1ok ? *(const uint2*)(Bp + v + HW)  : z2;
    uint2 Bhm = h0ok ? *(const uint2*)(Bp + v - 256) : z2;
    uint2 Bhp = h1ok ? *(const uint2*)(Bp + v + 256) : z2;
    unsigned bL = w0ok ? *(const unsigned*)(Bp + v - 2) : 0u;
    unsigned bR = w1ok ? *(const unsigned*)(Bp + v + 4) : 0u;

    unsigned tc4 = *(const unsigned*)(Tb + v);
    unsigned tdm = d0ok ? *(const unsigned*)(Tb + v - HW)  : 0u;
    unsigned tdp = d1ok ? *(const unsigned*)(Tb + v + HW)  : 0u;
    unsigned thm = h0ok ? *(const unsigned*)(Tb + v - 256) : 0u;
    unsigned thp = h1ok ? *(const unsigned*)(Tb + v + 256) : 0u;
    unsigned twL = w0ok ? *(const unsigned*)(Tb + v - 4)   : 0u;
    unsigned twR = w1ok ? *(const unsigned*)(Tb + v + 4)   : 0u;

    // ---- A stencil: per voxel j, half2 = classes (1,2) ----
    const __half2 m6 = __floats2half2_rn(-6.f, -6.f);
    const __half2* cA = (const __half2*)&Ac;
    __half2 sA[4];
    {
        const __half2* dm = (const __half2*)&Adm;
        const __half2* dp = (const __half2*)&Adp;
        const __half2* hm = (const __half2*)&Ahm;
        const __half2* hp = (const __half2*)&Ahp;
#pragma unroll
        for (int j = 0; j < 4; ++j) {
            __half2 lf = (j == 0) ? u2h(lfA) : cA[j - 1];
            __half2 rt = (j == 3) ? u2h(rtA) : cA[j + 1];
            __half2 s = __hadd2(__hadd2(dm[j], dp[j]), __hadd2(hm[j], hp[j]));
            s = __hadd2(s, __hadd2(lf, rt));
            sA[j] = __hfma2(cA[j], m6, s);
        }
    }

    // ---- B stencil: pairs (v0,v1) and (v2,v3), class 3 ----
    unsigned L0  = __byte_perm(Bc.x, bL, 0x1076);   // (B[v-1], v0)
    unsigned mid = __byte_perm(Bc.x, Bc.y, 0x5432); // (v1, v2)
    unsigned R1  = __byte_perm(Bc.y, bR, 0x5432);   // (v3, B[v+4])
    __half2 sB0 = __hadd2(__hadd2(u2h(Bdm.x), u2h(Bdp.x)),
                          __hadd2(u2h(Bhm.x), u2h(Bhp.x)));
    sB0 = __hadd2(sB0, __hadd2(u2h(L0), u2h(mid)));
    sB0 = __hfma2(u2h(Bc.x), m6, sB0);
    __half2 sB1 = __hadd2(__hadd2(u2h(Bdm.y), u2h(Bdp.y)),
                          __hadd2(u2h(Bhm.y), u2h(Bhp.y)));
    sB1 = __hadd2(sB1, __hadd2(u2h(mid), u2h(R1)));
    sB1 = __hfma2(u2h(Bc.y), m6, sB1);

    // ---- byte-SIMD target |Laplacian| per class (values 0..6 per byte) ----
    unsigned lt4 = __byte_perm(tc4, twL, 0x2107);
    unsigned rt4 = __byte_perm(tc4, twR, 0x4321);
    const unsigned ONE = 0x01010101u;
    unsigned absT[3];
#pragma unroll
    for (int c = 0; c < 3; ++c) {
        unsigned cc = ONE * (unsigned)(c + 1);
        unsigned cnt = (__vcmpeq4(tdm, cc) & ONE) + (__vcmpeq4(tdp, cc) & ONE)
                     + (__vcmpeq4(thm, cc) & ONE) + (__vcmpeq4(thp, cc) & ONE)
                     + (__vcmpeq4(lt4, cc) & ONE) + (__vcmpeq4(rt4, cc) & ONE);
        unsigned e = __vcmpeq4(tc4, cc);           // 0xFF where center == class
        absT[c] = (cnt & ~e) | ((0x06060606u - cnt) & e);
    }

    // ---- loss accumulation ----
    float acc = 0.f;
#pragma unroll
    for (int j = 0; j < 4; ++j) {
        float2 f12 = __half22float2(__habs2(sA[j]));
        __half2 sb = (j < 2) ? sB0 : sB1;
        float f3 = fabsf((j & 1) ? __half2float(__high2half(sb))
                                 : __half2float(__low2half(sb)));
        float t1 = (float)((absT[0] >> (j * 8)) & 0xFFu);
        float t2 = (float)((absT[1] >> (j * 8)) & 0xFFu);
        float t3 = (float)((absT[2] >> (j * 8)) & 0xFFu);
        float d1 = f12.x - t1, d2 = f12.y - t2, d3 = f3 - t3;
        acc = fmaf(d1, d1, acc);
        acc = fmaf(d2, d2, acc);
        acc = fmaf(d3, d3, acc);
    }

    // ---- block reduction -> double atomic -> last-block finalize ----
#pragma unroll
    for (int o = 16; o; o >>= 1) acc += __shfl_down_sync(0xffffffffu, acc, o);
    __shared__ float ws[8];
    __shared__ unsigned ticket;
    int lane = threadIdx.x & 31, wid = threadIdx.x >> 5;
    if (lane == 0) ws[wid] = acc;
    __syncthreads();
    if (wid == 0) {
        acc = (lane < 8) ? ws[lane] : 0.f;
#pragma unroll
        for (int o = 4; o; o >>= 1) acc += __shfl_down_sync(0xffffffffu, acc, o);
        if (lane == 0) {
            atomicAdd(&g_acc, (double)acc);
            __threadfence();
            ticket = atomicAdd(&g_done, 1u);
        }
    }
    __syncthreads();
    if (threadIdx.x == 0 && ticket == gridDim.x - 1) {
        double total = atomicAdd(&g_acc, 0.0);
        out[0] = (float)(total * (1.0 / NELEM));
        g_done = 0;
    }
}

extern "C" void kernel_launch(void* const* d_in, const int* in_sizes, int n_in,
                              void* d_out, int out_size) {
    const float* logits  = (const float*)d_in[0];
    const int*   targets = (const int*)d_in[1];
    float* out = (float*)d_out;

    softmax_kernel<<<NQ / 256, 256>>>(logits, targets);
    loss_kernel<<<NQ / 256, 256>>>(out);
}